// round 1
// baseline (speedup 1.0000x reference)
#include <cuda_runtime.h>
#include <cuda_bf16.h>
#include <math.h>
#include <stdint.h>

#define NS 305     // real states
#define SP 320     // padded states
#define NB 64      // batch
#define NT 4096    // time steps
#define NTAU 1023  // 4-gram steps (covers t=1..4092); tail: Q-step (4093,4094) + A-step (4095)

// ---------------- device globals (zero-initialized; pads never written stay 0) -------------
__device__ float g_I[SP];                                   // softmax(init)
__device__ float g_BmT[4][SP];                              // BmT[a][s] = Bm[s][a]
__device__ float g_A32[SP * SP];                            // softmax rows of transition
__device__ float g_Q32[4][SP * SP];                         // Q_a = A D_a A (fp32)
__device__ __align__(16) __nv_bfloat16 g_Abf[SP * SP];
__device__ __align__(16) __nv_bfloat16 g_Qbf[4][SP * SP];
__device__ __align__(16) __nv_bfloat16 g_Rbf[64][SP * SP];  // R_{abc} = Q_a D_b Q_c (bf16)
__device__ unsigned char g_gram[NB * NTAU];                 // (a<<6)|(b<<4)|(c<<2)|d
__device__ unsigned char g_o0[NB];
__device__ unsigned char g_tail[NB];                        // (a'<<4)|(b'<<2)|c'

__device__ __forceinline__ float warpSum(float x) {
    #pragma unroll
    for (int o = 16; o; o >>= 1) x += __shfl_down_sync(0xffffffffu, x, o);
    return x;
}
__device__ __forceinline__ float warpMax(float x) {
    #pragma unroll
    for (int o = 16; o; o >>= 1) x = fmaxf(x, __shfl_down_sync(0xffffffffu, x, o));
    return x;
}

// ---------------- setup: I softmax + emission softmax (transposed) ----------------
__global__ void k_setup(const float* __restrict__ initk, const float* __restrict__ emisk) {
    __shared__ float red[16];
    __shared__ float bval;
    int tid = threadIdx.x, wid = tid >> 5, lane = tid & 31;
    const int nw = 512 / 32;

    float v = (tid < NS) ? initk[tid] : -1e30f;
    float m = warpMax(v);
    if (lane == 0) red[wid] = m;
    __syncthreads();
    if (tid == 0) { float mm = -1e30f; for (int w = 0; w < nw; w++) mm = fmaxf(mm, red[w]); bval = mm; }
    __syncthreads();
    m = bval;
    float e = (tid < NS) ? expf(v - m) : 0.f;
    float s = warpSum(e);
    __syncthreads();                       // protect red from previous phase
    if (lane == 0) red[wid] = s;
    __syncthreads();
    if (tid == 0) { float ss = 0.f; for (int w = 0; w < nw; w++) ss += red[w]; bval = ss; }
    __syncthreads();
    if (tid < NS) g_I[tid] = e / bval;

    if (tid < NS) {
        float x0 = emisk[tid * 4 + 0], x1 = emisk[tid * 4 + 1];
        float x2 = emisk[tid * 4 + 2], x3 = emisk[tid * 4 + 3];
        float mm = fmaxf(fmaxf(x0, x1), fmaxf(x2, x3));
        float e0 = expf(x0 - mm), e1 = expf(x1 - mm), e2 = expf(x2 - mm), e3 = expf(x3 - mm);
        float inv = 1.f / (e0 + e1 + e2 + e3);
        g_BmT[0][tid] = e0 * inv;
        g_BmT[1][tid] = e1 * inv;
        g_BmT[2][tid] = e2 * inv;
        g_BmT[3][tid] = e3 * inv;
    }
}

// ---------------- softmax rows of transition -> A32 / Abf ----------------
__global__ void k_softA(const float* __restrict__ trans) {
    __shared__ float red[10];
    __shared__ float bval;
    int r = blockIdx.x;                 // 0..304
    int tid = threadIdx.x;              // 320 threads
    int wid = tid >> 5, lane = tid & 31;
    const int nw = 10;

    float v = (tid < NS) ? trans[r * NS + tid] : -1e30f;
    float m = warpMax(v);
    if (lane == 0) red[wid] = m;
    __syncthreads();
    if (tid == 0) { float mm = -1e30f; for (int w = 0; w < nw; w++) mm = fmaxf(mm, red[w]); bval = mm; }
    __syncthreads();
    m = bval;
    float e = (tid < NS) ? expf(v - m) : 0.f;
    float s = warpSum(e);
    __syncthreads();
    if (lane == 0) red[wid] = s;
    __syncthreads();
    if (tid == 0) { float ss = 0.f; for (int w = 0; w < nw; w++) ss += red[w]; bval = ss; }
    __syncthreads();
    if (tid < NS) {
        float p = e / bval;
        g_A32[r * SP + tid] = p;
        g_Abf[r * SP + tid] = __float2bfloat16(p);
    }
}

// ---------------- observation -> gram indices ----------------
__global__ void k_gram(const float* __restrict__ inputs) {
    int b = blockIdx.x;
    const float* inb = inputs + (size_t)b * NT * 4;
    for (int tau = threadIdx.x; tau < NTAU; tau += blockDim.x) {
        int t0 = 1 + 4 * tau;
        unsigned g = 0;
        #pragma unroll
        for (int k = 0; k < 4; k++) {
            const float* p = inb + (size_t)(t0 + k) * 4;
            float fi = p[1] + 2.f * p[2] + 3.f * p[3];  // exact argmax of one-hot
            g = (g << 2) | (unsigned)(fi + 0.5f);
        }
        g_gram[b * NTAU + tau] = (unsigned char)g;
    }
    if (threadIdx.x == 0) {
        const float* p = inb;
        g_o0[b] = (unsigned char)(p[1] + 2.f * p[2] + 3.f * p[3] + 0.5f);
        unsigned tg = 0;
        #pragma unroll
        for (int k = 0; k < 3; k++) {
            const float* q = inb + (size_t)(4093 + k) * 4;
            tg = (tg << 2) | (unsigned)(q[1] + 2.f * q[2] + 3.f * q[3] + 0.5f);
        }
        g_tail[b] = (unsigned char)tg;
    }
}

// ---------------- tiled fp32 GEMM with k-dim column scaling ----------------
// C = (L * diag(sc)) @ R, all [320,320]. mode 0: Q_a; mode 1: R_{abc}.
__global__ void __launch_bounds__(256) k_gemm(int mode) {
    int z = blockIdx.z;
    const float *Lp, *Rp, *sc;
    float* outf = nullptr;
    __nv_bfloat16* outb;
    if (mode == 0) {
        Lp = g_A32; Rp = g_A32; sc = g_BmT[z]; outf = g_Q32[z]; outb = g_Qbf[z];
    } else {
        int a = z >> 4, bb = (z >> 2) & 3, c = z & 3;
        Lp = g_Q32[a]; sc = g_BmT[bb]; Rp = g_Q32[c]; outb = g_Rbf[z];
    }
    int m0 = blockIdx.y * 64, n0 = blockIdx.x * 64;

    __shared__ float Ls[16][64];
    __shared__ float Rs[16][64];
    int tid = threadIdx.x;
    int tx = tid & 15, ty = tid >> 4;
    int lrow = tid >> 2, lk = (tid & 3) * 4;
    int rk = tid >> 4, rn = (tid & 15) * 4;

    float acc[4][4] = {};
    for (int k0 = 0; k0 < SP; k0 += 16) {
        float4 lv = *(const float4*)&Lp[(size_t)(m0 + lrow) * SP + k0 + lk];
        Ls[lk + 0][lrow] = lv.x * sc[k0 + lk + 0];
        Ls[lk + 1][lrow] = lv.y * sc[k0 + lk + 1];
        Ls[lk + 2][lrow] = lv.z * sc[k0 + lk + 2];
        Ls[lk + 3][lrow] = lv.w * sc[k0 + lk + 3];
        *(float4*)&Rs[rk][rn] = *(const float4*)&Rp[(size_t)(k0 + rk) * SP + n0 + rn];
        __syncthreads();
        #pragma unroll
        for (int kk = 0; kk < 16; kk++) {
            float a0 = Ls[kk][ty * 4 + 0], a1 = Ls[kk][ty * 4 + 1];
            float a2 = Ls[kk][ty * 4 + 2], a3 = Ls[kk][ty * 4 + 3];
            float4 bv = *(const float4*)&Rs[kk][tx * 4];
            acc[0][0] = fmaf(a0, bv.x, acc[0][0]); acc[0][1] = fmaf(a0, bv.y, acc[0][1]);
            acc[0][2] = fmaf(a0, bv.z, acc[0][2]); acc[0][3] = fmaf(a0, bv.w, acc[0][3]);
            acc[1][0] = fmaf(a1, bv.x, acc[1][0]); acc[1][1] = fmaf(a1, bv.y, acc[1][1]);
            acc[1][2] = fmaf(a1, bv.z, acc[1][2]); acc[1][3] = fmaf(a1, bv.w, acc[1][3]);
            acc[2][0] = fmaf(a2, bv.x, acc[2][0]); acc[2][1] = fmaf(a2, bv.y, acc[2][1]);
            acc[2][2] = fmaf(a2, bv.z, acc[2][2]); acc[2][3] = fmaf(a2, bv.w, acc[2][3]);
            acc[3][0] = fmaf(a3, bv.x, acc[3][0]); acc[3][1] = fmaf(a3, bv.y, acc[3][1]);
            acc[3][2] = fmaf(a3, bv.z, acc[3][2]); acc[3][3] = fmaf(a3, bv.w, acc[3][3]);
        }
        __syncthreads();
    }
    #pragma unroll
    for (int i = 0; i < 4; i++) {
        #pragma unroll
        for (int j = 0; j < 4; j++) {
            size_t idx = (size_t)(m0 + ty * 4 + i) * SP + (n0 + tx * 4 + j);
            if (outf) outf[idx] = acc[i][j];
            outb[idx] = __float2bfloat16(acc[i][j]);
        }
    }
}

// ---------------- chain: per-batch persistent CTA, 1025 matvec steps ----------------
__global__ void __launch_bounds__(640, 1) k_chain(float* __restrict__ out) {
    int b = blockIdx.x, tid = threadIdx.x;
    __shared__ float alpha[SP];
    __shared__ float part[8][SP];
    __shared__ float red[20];
    __shared__ float sinv;
    int wid = tid >> 5, lane = tid & 31;
    int jq = tid % 80;        // j = 4*jq .. 4*jq+3
    int iq = tid / 80;        // 0..7
    int i0 = iq * 40;
    int i1 = min(i0 + 40, NS);

    double ll = 0.0;

    // t = 0 prologue: alpha0 = I * Bm[:, o0], normalized
    int o0 = g_o0[b];
    float v = (tid < SP) ? g_I[tid] * g_BmT[o0][tid] : 0.f;
    float ws = warpSum(v);
    if (lane == 0) red[wid] = ws;
    __syncthreads();
    if (tid == 0) {
        float ss = 0.f;
        #pragma unroll
        for (int w = 0; w < 20; w++) ss += red[w];
        sinv = 1.f / ss;
        ll = log((double)ss);
    }
    __syncthreads();
    if (tid < SP) alpha[tid] = v * sinv;
    __syncthreads();

    unsigned tg = g_tail[b];
    for (int step = 0; step < NTAU + 2; ++step) {
        const __nv_bfloat16* Mp;
        int d;
        if (step < NTAU) {
            unsigned g = g_gram[b * NTAU + step];
            Mp = g_Rbf[g >> 2];
            d = g & 3;
        } else if (step == NTAU) {
            Mp = g_Qbf[(tg >> 4) & 3];
            d = (tg >> 2) & 3;
        } else {
            Mp = g_Abf;
            d = tg & 3;
        }
        const float* fold = g_BmT[d];

        // partial matvec: this thread covers columns [4jq..4jq+3], rows [i0, i1)
        const uint2* p = (const uint2*)Mp + (size_t)i0 * 80 + jq;
        float a0 = 0.f, a1 = 0.f, a2 = 0.f, a3 = 0.f;
        #pragma unroll 5
        for (int i = i0; i < i1; ++i) {
            float av = alpha[i];
            uint2 w = *p;
            p += 80;
            a0 = fmaf(av, __int_as_float((int)(w.x << 16)), a0);
            a1 = fmaf(av, __int_as_float((int)(w.x & 0xffff0000u)), a1);
            a2 = fmaf(av, __int_as_float((int)(w.y << 16)), a2);
            a3 = fmaf(av, __int_as_float((int)(w.y & 0xffff0000u)), a3);
        }
        *(float4*)&part[iq][4 * jq] = make_float4(a0, a1, a2, a3);
        __syncthreads();

        float val = 0.f;
        if (tid < SP) {
            val = ((part[0][tid] + part[1][tid]) + (part[2][tid] + part[3][tid])) +
                  ((part[4][tid] + part[5][tid]) + (part[6][tid] + part[7][tid]));
            val *= fold[tid];
        }
        float w2 = warpSum(val);
        if (lane == 0) red[wid] = w2;
        __syncthreads();
        if (tid == 0) {
            float ss = 0.f;
            #pragma unroll
            for (int w = 0; w < 20; w++) ss += red[w];
            sinv = 1.f / ss;
            ll += log((double)ss);
        }
        __syncthreads();
        if (tid < SP) alpha[tid] = val * sinv;
        __syncthreads();
    }
    if (tid == 0) out[b] = (float)ll;
}

// ---------------- launch ----------------
extern "C" void kernel_launch(void* const* d_in, const int* in_sizes, int n_in,
                              void* d_out, int out_size) {
    const float* inputs = (const float*)d_in[0];   // [64,4096,4] one-hot
    const float* initk  = (const float*)d_in[1];   // [305]
    const float* transk = (const float*)d_in[2];   // [305,305]
    const float* emisk  = (const float*)d_in[3];   // [305,4]
    float* out = (float*)d_out;                    // [64]

    k_setup<<<1, 512>>>(initk, emisk);
    k_softA<<<NS, 320>>>(transk);
    k_gram<<<NB, 256>>>(inputs);
    k_gemm<<<dim3(5, 5, 4), 256>>>(0);    // Q_a = (A*D_a) @ A
    k_gemm<<<dim3(5, 5, 64), 256>>>(1);   // R_abc = (Q_a*D_b) @ Q_c
    k_chain<<<NB, 640>>>(out);
}

// round 2
// speedup vs baseline: 1.3170x; 1.3170x over previous
#include <cuda_runtime.h>
#include <cuda_fp16.h>
#include <math.h>
#include <stdint.h>

#define NS 305     // real states
#define SP 320     // padded states
#define NB 64      // batch
#define NT 4096    // time steps
#define NTAU 1023  // 4-gram steps (t=1..4092); tail: Q-step (4093,4094) + A-step (4095)

#define SCALEF 4096.0f
// log(4096) in double
#define LOG_SCALE_D 8.317766166719343

// ---------------- device globals (zero-initialized; pads stay 0) -------------
__device__ float g_I[SP];                                   // softmax(init)
__device__ float g_BmT[4][SP];                              // BmT[a][s] = Bm[s][a]
__device__ float g_A32[SP * SP];                            // softmax rows of transition
__device__ float g_Q32[4][SP * SP];                         // Q_a = A D_a A (fp32)
__device__ __align__(16) __half g_Ah[SP * SP];              // A * SCALE (fp16)
__device__ __align__(16) __half g_Qh[4][SP * SP];           // Q_a * SCALE (fp16)
__device__ __align__(16) __half g_Rh[64][SP * SP];          // R_{abc} * SCALE (fp16)
__device__ unsigned char g_gram[NB * NTAU];                 // (a<<6)|(b<<4)|(c<<2)|d
__device__ unsigned char g_o0[NB];
__device__ unsigned char g_tail[NB];                        // (a'<<4)|(b'<<2)|c'

__device__ __forceinline__ float warpSum(float x) {
    #pragma unroll
    for (int o = 16; o; o >>= 1) x += __shfl_down_sync(0xffffffffu, x, o);
    return x;
}
__device__ __forceinline__ float warpMax(float x) {
    #pragma unroll
    for (int o = 16; o; o >>= 1) x = fmaxf(x, __shfl_down_sync(0xffffffffu, x, o));
    return x;
}

// ---------------- setup: I softmax + emission softmax (transposed) ----------------
__global__ void k_setup(const float* __restrict__ initk, const float* __restrict__ emisk) {
    __shared__ float red[16];
    __shared__ float bval;
    int tid = threadIdx.x, wid = tid >> 5, lane = tid & 31;
    const int nw = 512 / 32;

    float v = (tid < NS) ? initk[tid] : -1e30f;
    float m = warpMax(v);
    if (lane == 0) red[wid] = m;
    __syncthreads();
    if (tid == 0) { float mm = -1e30f; for (int w = 0; w < nw; w++) mm = fmaxf(mm, red[w]); bval = mm; }
    __syncthreads();
    m = bval;
    float e = (tid < NS) ? expf(v - m) : 0.f;
    float s = warpSum(e);
    __syncthreads();
    if (lane == 0) red[wid] = s;
    __syncthreads();
    if (tid == 0) { float ss = 0.f; for (int w = 0; w < nw; w++) ss += red[w]; bval = ss; }
    __syncthreads();
    if (tid < NS) g_I[tid] = e / bval;

    if (tid < NS) {
        float x0 = emisk[tid * 4 + 0], x1 = emisk[tid * 4 + 1];
        float x2 = emisk[tid * 4 + 2], x3 = emisk[tid * 4 + 3];
        float mm = fmaxf(fmaxf(x0, x1), fmaxf(x2, x3));
        float e0 = expf(x0 - mm), e1 = expf(x1 - mm), e2 = expf(x2 - mm), e3 = expf(x3 - mm);
        float inv = 1.f / (e0 + e1 + e2 + e3);
        g_BmT[0][tid] = e0 * inv;
        g_BmT[1][tid] = e1 * inv;
        g_BmT[2][tid] = e2 * inv;
        g_BmT[3][tid] = e3 * inv;
    }
}

// ---------------- softmax rows of transition -> A32 / Ah ----------------
__global__ void k_softA(const float* __restrict__ trans) {
    __shared__ float red[10];
    __shared__ float bval;
    int r = blockIdx.x;                 // 0..304
    int tid = threadIdx.x;              // 320 threads
    int wid = tid >> 5, lane = tid & 31;
    const int nw = 10;

    float v = (tid < NS) ? trans[r * NS + tid] : -1e30f;
    float m = warpMax(v);
    if (lane == 0) red[wid] = m;
    __syncthreads();
    if (tid == 0) { float mm = -1e30f; for (int w = 0; w < nw; w++) mm = fmaxf(mm, red[w]); bval = mm; }
    __syncthreads();
    m = bval;
    float e = (tid < NS) ? expf(v - m) : 0.f;
    float s = warpSum(e);
    __syncthreads();
    if (lane == 0) red[wid] = s;
    __syncthreads();
    if (tid == 0) { float ss = 0.f; for (int w = 0; w < nw; w++) ss += red[w]; bval = ss; }
    __syncthreads();
    if (tid < NS) {
        float p = e / bval;
        g_A32[r * SP + tid] = p;
        g_Ah[r * SP + tid] = __float2half_rn(p * SCALEF);
    }
}

// ---------------- observation -> gram indices ----------------
__global__ void k_gram(const float* __restrict__ inputs) {
    int b = blockIdx.x;
    const float* inb = inputs + (size_t)b * NT * 4;
    for (int tau = threadIdx.x; tau < NTAU; tau += blockDim.x) {
        int t0 = 1 + 4 * tau;
        unsigned g = 0;
        #pragma unroll
        for (int k = 0; k < 4; k++) {
            const float* p = inb + (size_t)(t0 + k) * 4;
            float fi = p[1] + 2.f * p[2] + 3.f * p[3];  // exact argmax of one-hot
            g = (g << 2) | (unsigned)(fi + 0.5f);
        }
        g_gram[b * NTAU + tau] = (unsigned char)g;
    }
    if (threadIdx.x == 0) {
        const float* p = inb;
        g_o0[b] = (unsigned char)(p[1] + 2.f * p[2] + 3.f * p[3] + 0.5f);
        unsigned tg = 0;
        #pragma unroll
        for (int k = 0; k < 3; k++) {
            const float* q = inb + (size_t)(4093 + k) * 4;
            tg = (tg << 2) | (unsigned)(q[1] + 2.f * q[2] + 3.f * q[3] + 0.5f);
        }
        g_tail[b] = (unsigned char)tg;
    }
}

// ---------------- tiled fp32 GEMM with k-dim column scaling ----------------
// C = (L * diag(sc)) @ R, all [320,320]. mode 0: Q_a; mode 1: R_{abc}.
__global__ void __launch_bounds__(256) k_gemm(int mode) {
    int z = blockIdx.z;
    const float *Lp, *Rp, *sc;
    float* outf = nullptr;
    __half* outh;
    if (mode == 0) {
        Lp = g_A32; Rp = g_A32; sc = g_BmT[z]; outf = g_Q32[z]; outh = g_Qh[z];
    } else {
        int a = z >> 4, bb = (z >> 2) & 3, c = z & 3;
        Lp = g_Q32[a]; sc = g_BmT[bb]; Rp = g_Q32[c]; outh = g_Rh[z];
    }
    int m0 = blockIdx.y * 64, n0 = blockIdx.x * 64;

    __shared__ float Ls[16][64];
    __shared__ float Rs[16][64];
    int tid = threadIdx.x;
    int tx = tid & 15, ty = tid >> 4;
    int lrow = tid >> 2, lk = (tid & 3) * 4;
    int rk = tid >> 4, rn = (tid & 15) * 4;

    float acc[4][4] = {};
    for (int k0 = 0; k0 < SP; k0 += 16) {
        float4 lv = *(const float4*)&Lp[(size_t)(m0 + lrow) * SP + k0 + lk];
        Ls[lk + 0][lrow] = lv.x * sc[k0 + lk + 0];
        Ls[lk + 1][lrow] = lv.y * sc[k0 + lk + 1];
        Ls[lk + 2][lrow] = lv.z * sc[k0 + lk + 2];
        Ls[lk + 3][lrow] = lv.w * sc[k0 + lk + 3];
        *(float4*)&Rs[rk][rn] = *(const float4*)&Rp[(size_t)(k0 + rk) * SP + n0 + rn];
        __syncthreads();
        #pragma unroll
        for (int kk = 0; kk < 16; kk++) {
            float a0 = Ls[kk][ty * 4 + 0], a1 = Ls[kk][ty * 4 + 1];
            float a2 = Ls[kk][ty * 4 + 2], a3 = Ls[kk][ty * 4 + 3];
            float4 bv = *(const float4*)&Rs[kk][tx * 4];
            acc[0][0] = fmaf(a0, bv.x, acc[0][0]); acc[0][1] = fmaf(a0, bv.y, acc[0][1]);
            acc[0][2] = fmaf(a0, bv.z, acc[0][2]); acc[0][3] = fmaf(a0, bv.w, acc[0][3]);
            acc[1][0] = fmaf(a1, bv.x, acc[1][0]); acc[1][1] = fmaf(a1, bv.y, acc[1][1]);
            acc[1][2] = fmaf(a1, bv.z, acc[1][2]); acc[1][3] = fmaf(a1, bv.w, acc[1][3]);
            acc[2][0] = fmaf(a2, bv.x, acc[2][0]); acc[2][1] = fmaf(a2, bv.y, acc[2][1]);
            acc[2][2] = fmaf(a2, bv.z, acc[2][2]); acc[2][3] = fmaf(a2, bv.w, acc[2][3]);
            acc[3][0] = fmaf(a3, bv.x, acc[3][0]); acc[3][1] = fmaf(a3, bv.y, acc[3][1]);
            acc[3][2] = fmaf(a3, bv.z, acc[3][2]); acc[3][3] = fmaf(a3, bv.w, acc[3][3]);
        }
        __syncthreads();
    }
    #pragma unroll
    for (int i = 0; i < 4; i++) {
        #pragma unroll
        for (int j = 0; j < 4; j++) {
            size_t idx = (size_t)(m0 + ty * 4 + i) * SP + (n0 + tx * 4 + j);
            if (outf) outf[idx] = acc[i][j];
            outh[idx] = __float2half_rn(acc[i][j] * SCALEF);
        }
    }
}

// ---------------- chain: per-batch persistent CTA, 1025 fp16 matvec steps ----------------
// 640 threads: jq = tid%40 covers cols [8jq..8jq+7]; iq = tid/40 covers rows [20iq..20iq+19].
__global__ void __launch_bounds__(640, 1) k_chain(float* __restrict__ out) {
    int b = blockIdx.x, tid = threadIdx.x;
    __shared__ uint32_t part[16][160];      // f16x2 partials, [iq][col-pair]
    __shared__ __half2 ah2[SP];             // alpha duplicated pairs (a_i, a_i)
    __shared__ float red[20];
    __shared__ float sinv_s;
    __shared__ float ssave_s;
    int wid = tid >> 5, lane = tid & 31;
    int jq = tid % 40;
    int iq = tid / 40;
    int i0 = iq * 20;

    double ll = 0.0;

    // ---- t = 0 prologue: alpha0 = I * Bm[:, o0], normalized (fp32, unscaled) ----
    int o0 = g_o0[b];
    float v = (tid < SP) ? g_I[tid] * g_BmT[o0][tid] : 0.f;
    float ws = warpSum(v);
    if (lane == 0) red[wid] = ws;
    __syncthreads();
    if (wid == 0) {
        float x = (lane < 20) ? red[lane] : 0.f;
        x = warpSum(x);
        if (lane == 0) { sinv_s = 1.f / x; ssave_s = x; }
    }
    __syncthreads();
    if (tid == 0) ll = log((double)ssave_s);
    float* af = (float*)part;               // reuse part space for fp32 handoff
    if (tid < SP) af[tid] = v * sinv_s;
    __syncthreads();
    if (tid < 160) {
        float a0 = af[2 * tid], a1 = af[2 * tid + 1];
        ah2[2 * tid]     = __floats2half2_rn(a0, a0);
        ah2[2 * tid + 1] = __floats2half2_rn(a1, a1);
    }
    __syncthreads();

    unsigned tg = g_tail[b];
    for (int step = 0; step < NTAU + 2; ++step) {
        const __half* Mp;
        int d;
        if (step < NTAU) {
            unsigned g = g_gram[b * NTAU + step];
            Mp = g_Rh[g >> 2];
            d = g & 3;
        } else if (step == NTAU) {
            Mp = g_Qh[(tg >> 4) & 3];
            d = (tg >> 2) & 3;
        } else {
            Mp = g_Ah;
            d = tg & 3;
        }
        const float* fold = g_BmT[d];

        // partial matvec: rows [i0, i0+20), cols [8jq, 8jq+8)
        const uint4* p = (const uint4*)(Mp + (size_t)i0 * SP) + jq;
        __half2 c0 = __floats2half2_rn(0.f, 0.f);
        __half2 c1 = c0, c2 = c0, c3 = c0;
        #pragma unroll
        for (int i = 0; i < 20; ++i) {
            uint4 w = __ldcg(&p[(size_t)i * 40]);   // row stride = 320 halves = 40 uint4
            __half2 av = ah2[i0 + i];
            c0 = __hfma2(av, *reinterpret_cast<__half2*>(&w.x), c0);
            c1 = __hfma2(av, *reinterpret_cast<__half2*>(&w.y), c1);
            c2 = __hfma2(av, *reinterpret_cast<__half2*>(&w.z), c2);
            c3 = __hfma2(av, *reinterpret_cast<__half2*>(&w.w), c3);
        }
        uint4 pk;
        pk.x = *reinterpret_cast<uint32_t*>(&c0);
        pk.y = *reinterpret_cast<uint32_t*>(&c1);
        pk.z = *reinterpret_cast<uint32_t*>(&c2);
        pk.w = *reinterpret_cast<uint32_t*>(&c3);
        *reinterpret_cast<uint4*>(&part[iq][jq * 4]) = pk;
        __syncthreads();

        // reduce 16 partials per column pair, apply fold, get scaled s
        float v0 = 0.f, v1 = 0.f;
        if (tid < 160) {
            __half2 s2 = __floats2half2_rn(0.f, 0.f);
            #pragma unroll
            for (int k = 0; k < 16; ++k)
                s2 = __hadd2(s2, *reinterpret_cast<const __half2*>(&part[k][tid]));
            float2 f2 = __half22float2(s2);
            v0 = f2.x * fold[2 * tid];
            v1 = f2.y * fold[2 * tid + 1];
        }
        float t = warpSum(v0 + v1);
        if (lane == 0) red[wid] = t;
        __syncthreads();
        if (wid == 0) {
            float x = (lane < 20) ? red[lane] : 0.f;
            x = warpSum(x);
            if (lane == 0) { sinv_s = 1.f / x; ssave_s = x; }
        }
        __syncthreads();
        if (tid < 160) {
            float si = sinv_s;
            float a0 = v0 * si, a1 = v1 * si;
            ah2[2 * tid]     = __floats2half2_rn(a0, a0);
            ah2[2 * tid + 1] = __floats2half2_rn(a1, a1);
        }
        if (tid == 0) ll += log((double)ssave_s);   // off the alpha critical path
        __syncthreads();
    }
    if (tid == 0) out[b] = (float)(ll - (double)(NTAU + 2) * LOG_SCALE_D);
}

// ---------------- launch ----------------
extern "C" void kernel_launch(void* const* d_in, const int* in_sizes, int n_in,
                              void* d_out, int out_size) {
    const float* inputs = (const float*)d_in[0];   // [64,4096,4] one-hot
    const float* initk  = (const float*)d_in[1];   // [305]
    const float* transk = (const float*)d_in[2];   // [305,305]
    const float* emisk  = (const float*)d_in[3];   // [305,4]
    float* out = (float*)d_out;                    // [64]

    k_setup<<<1, 512>>>(initk, emisk);
    k_softA<<<NS, 320>>>(transk);
    k_gram<<<NB, 256>>>(inputs);
    k_gemm<<<dim3(5, 5, 4), 256>>>(0);    // Q_a = (A*D_a) @ A
    k_gemm<<<dim3(5, 5, 64), 256>>>(1);   // R_abc = (Q_a*D_b) @ Q_c   (fp16 * SCALE)
    k_chain<<<NB, 640>>>(out);
}

// round 3
// speedup vs baseline: 2.2596x; 1.7156x over previous
#include <cuda_runtime.h>
#include <cuda_fp16.h>
#include <cuda_fp8.h>
#include <math.h>
#include <stdint.h>

#define NS 305
#define SP 320
#define SPSP (SP * SP)
#define NB 64
#define NT 4096
#define NTAU 1023            // 4-gram steps (t=1..4092)
#define NSTEP (NTAU + 2)     // + Q-step + A-step
#define LOG_SCALE_D 8.317766166719343   // log(4096)

// ---------------- device globals (zero-initialized) ----------------
__device__ float g_I[SP];
__device__ __align__(16) float g_BmT[4][SP];            // BmT[a][s] = Bm[s][a]
__device__ __align__(16) float g_A32[SPSP];
__device__ __align__(16) float g_Q32[4][SPSP];
__device__ __align__(16) float g_R32[64 * SPSP];        // fp32 R_{abc}
__device__ __align__(16) unsigned char g_S[69 * SPSP];  // fp8 e4m3: 64 R, 4 Q, 1 A
__device__ __align__(16) float g_rs[69 * SP];           // alpha row multiplier 4096/q
__device__ unsigned char g_gram[NB * NTAU];
__device__ unsigned char g_o0[NB];
__device__ unsigned char g_tail[NB];

__device__ __forceinline__ float warpSum(float x) {
    #pragma unroll
    for (int o = 16; o; o >>= 1) x += __shfl_down_sync(0xffffffffu, x, o);
    return x;
}
__device__ __forceinline__ float warpMax(float x) {
    #pragma unroll
    for (int o = 16; o; o >>= 1) x = fmaxf(x, __shfl_down_sync(0xffffffffu, x, o));
    return x;
}

// fp8x4 (packed in u32) -> 2x half2 (as u32 bit patterns)
__device__ __forceinline__ void cvt2(uint32_t w, uint32_t& h0, uint32_t& h1) {
    asm("{\n\t"
        ".reg .b16 lo, hi;\n\t"
        "mov.b32 {lo, hi}, %2;\n\t"
        "cvt.rn.f16x2.e4m3x2 %0, lo;\n\t"
        "cvt.rn.f16x2.e4m3x2 %1, hi;\n\t"
        "}" : "=r"(h0), "=r"(h1) : "r"(w));
}
__device__ __forceinline__ __half2 u2h(uint32_t u) { return *reinterpret_cast<__half2*>(&u); }
__device__ __forceinline__ uint32_t h2u(__half2 h) { return *reinterpret_cast<uint32_t*>(&h); }

#define BAR_SYNC(id, n)   asm volatile("bar.sync %0, %1;"   :: "n"(id), "n"(n) : "memory")
#define BAR_ARRIVE(id, n) asm volatile("bar.arrive %0, %1;" :: "n"(id), "n"(n) : "memory")

// ---------------- setup: I softmax + emission softmax ----------------
__global__ void k_setup(const float* __restrict__ initk, const float* __restrict__ emisk) {
    __shared__ float red[16];
    __shared__ float bval;
    int tid = threadIdx.x, wid = tid >> 5, lane = tid & 31;
    const int nw = 16;
    float v = (tid < NS) ? initk[tid] : -1e30f;
    float m = warpMax(v);
    if (lane == 0) red[wid] = m;
    __syncthreads();
    if (tid == 0) { float mm = -1e30f; for (int w = 0; w < nw; w++) mm = fmaxf(mm, red[w]); bval = mm; }
    __syncthreads();
    m = bval;
    float e = (tid < NS) ? expf(v - m) : 0.f;
    float s = warpSum(e);
    __syncthreads();
    if (lane == 0) red[wid] = s;
    __syncthreads();
    if (tid == 0) { float ss = 0.f; for (int w = 0; w < nw; w++) ss += red[w]; bval = ss; }
    __syncthreads();
    if (tid < NS) g_I[tid] = e / bval;

    if (tid < NS) {
        float x0 = emisk[tid * 4 + 0], x1 = emisk[tid * 4 + 1];
        float x2 = emisk[tid * 4 + 2], x3 = emisk[tid * 4 + 3];
        float mm = fmaxf(fmaxf(x0, x1), fmaxf(x2, x3));
        float e0 = expf(x0 - mm), e1 = expf(x1 - mm), e2 = expf(x2 - mm), e3 = expf(x3 - mm);
        float inv = 1.f / (e0 + e1 + e2 + e3);
        g_BmT[0][tid] = e0 * inv; g_BmT[1][tid] = e1 * inv;
        g_BmT[2][tid] = e2 * inv; g_BmT[3][tid] = e3 * inv;
    }
}

// ---------------- softmax rows of transition -> A32 ----------------
__global__ void k_softA(const float* __restrict__ trans) {
    __shared__ float red[10];
    __shared__ float bval;
    int r = blockIdx.x, tid = threadIdx.x;
    int wid = tid >> 5, lane = tid & 31;
    float v = (tid < NS) ? trans[r * NS + tid] : -1e30f;
    float m = warpMax(v);
    if (lane == 0) red[wid] = m;
    __syncthreads();
    if (tid == 0) { float mm = -1e30f; for (int w = 0; w < 10; w++) mm = fmaxf(mm, red[w]); bval = mm; }
    __syncthreads();
    m = bval;
    float e = (tid < NS) ? expf(v - m) : 0.f;
    float s = warpSum(e);
    __syncthreads();
    if (lane == 0) red[wid] = s;
    __syncthreads();
    if (tid == 0) { float ss = 0.f; for (int w = 0; w < 10; w++) ss += red[w]; bval = ss; }
    __syncthreads();
    if (tid < NS) g_A32[r * SP + tid] = e / bval;
}

// ---------------- observation -> gram indices ----------------
__global__ void k_gram(const float* __restrict__ inputs) {
    int b = blockIdx.x;
    const float* inb = inputs + (size_t)b * NT * 4;
    for (int tau = threadIdx.x; tau < NTAU; tau += blockDim.x) {
        int t0 = 1 + 4 * tau;
        unsigned g = 0;
        #pragma unroll
        for (int k = 0; k < 4; k++) {
            const float* p = inb + (size_t)(t0 + k) * 4;
            float fi = p[1] + 2.f * p[2] + 3.f * p[3];
            g = (g << 2) | (unsigned)(fi + 0.5f);
        }
        g_gram[b * NTAU + tau] = (unsigned char)g;
    }
    if (threadIdx.x == 0) {
        const float* p = inb;
        g_o0[b] = (unsigned char)(p[1] + 2.f * p[2] + 3.f * p[3] + 0.5f);
        unsigned tg = 0;
        #pragma unroll
        for (int k = 0; k < 3; k++) {
            const float* q = inb + (size_t)(4093 + k) * 4;
            tg = (tg << 2) | (unsigned)(q[1] + 2.f * q[2] + 3.f * q[3] + 0.5f);
        }
        g_tail[b] = (unsigned char)tg;
    }
}

// ---------------- fp32 GEMM with k-dim column scaling ----------------
// mode 0: Q_z = (A*D_z) @ A ; mode 1: R_z = (Q_a*D_b) @ Q_c
__global__ void __launch_bounds__(256) k_gemm(int mode) {
    int z = blockIdx.z;
    const float *Lp, *Rp, *sc;
    float* outf;
    if (mode == 0) {
        Lp = g_A32; Rp = g_A32; sc = g_BmT[z]; outf = g_Q32[z];
    } else {
        int a = z >> 4, bb = (z >> 2) & 3, c = z & 3;
        Lp = g_Q32[a]; sc = g_BmT[bb]; Rp = g_Q32[c]; outf = g_R32 + (size_t)z * SPSP;
    }
    int m0 = blockIdx.y * 64, n0 = blockIdx.x * 64;
    __shared__ float Ls[16][64];
    __shared__ float Rs[16][64];
    int tid = threadIdx.x;
    int tx = tid & 15, ty = tid >> 4;
    int lrow = tid >> 2, lk = (tid & 3) * 4;
    int rk = tid >> 4, rn = (tid & 15) * 4;

    float acc[4][4] = {};
    for (int k0 = 0; k0 < SP; k0 += 16) {
        float4 lv = *(const float4*)&Lp[(size_t)(m0 + lrow) * SP + k0 + lk];
        Ls[lk + 0][lrow] = lv.x * sc[k0 + lk + 0];
        Ls[lk + 1][lrow] = lv.y * sc[k0 + lk + 1];
        Ls[lk + 2][lrow] = lv.z * sc[k0 + lk + 2];
        Ls[lk + 3][lrow] = lv.w * sc[k0 + lk + 3];
        *(float4*)&Rs[rk][rn] = *(const float4*)&Rp[(size_t)(k0 + rk) * SP + n0 + rn];
        __syncthreads();
        #pragma unroll
        for (int kk = 0; kk < 16; kk++) {
            float a0 = Ls[kk][ty * 4 + 0], a1 = Ls[kk][ty * 4 + 1];
            float a2 = Ls[kk][ty * 4 + 2], a3 = Ls[kk][ty * 4 + 3];
            float4 bv = *(const float4*)&Rs[kk][tx * 4];
            acc[0][0] = fmaf(a0, bv.x, acc[0][0]); acc[0][1] = fmaf(a0, bv.y, acc[0][1]);
            acc[0][2] = fmaf(a0, bv.z, acc[0][2]); acc[0][3] = fmaf(a0, bv.w, acc[0][3]);
            acc[1][0] = fmaf(a1, bv.x, acc[1][0]); acc[1][1] = fmaf(a1, bv.y, acc[1][1]);
            acc[1][2] = fmaf(a1, bv.z, acc[1][2]); acc[1][3] = fmaf(a1, bv.w, acc[1][3]);
            acc[2][0] = fmaf(a2, bv.x, acc[2][0]); acc[2][1] = fmaf(a2, bv.y, acc[2][1]);
            acc[2][2] = fmaf(a2, bv.z, acc[2][2]); acc[2][3] = fmaf(a2, bv.w, acc[2][3]);
            acc[3][0] = fmaf(a3, bv.x, acc[3][0]); acc[3][1] = fmaf(a3, bv.y, acc[3][1]);
            acc[3][2] = fmaf(a3, bv.z, acc[3][2]); acc[3][3] = fmaf(a3, bv.w, acc[3][3]);
        }
        __syncthreads();
    }
    #pragma unroll
    for (int i = 0; i < 4; i++)
        #pragma unroll
        for (int j = 0; j < 4; j++)
            outf[(size_t)(m0 + ty * 4 + i) * SP + (n0 + tx * 4 + j)] = acc[i][j];
}

// ---------------- quantize to fp8 with per-row scale ----------------
__global__ void k_quant() {
    int r = blockIdx.x, z = blockIdx.y, tid = threadIdx.x;
    const float* src;
    if (z < 64) src = g_R32 + (size_t)z * SPSP;
    else if (z < 68) src = g_Q32[z - 64];
    else src = g_A32;
    float v = src[(size_t)r * SP + tid];
    __shared__ float red[10];
    __shared__ float bmax;
    int wid = tid >> 5, lane = tid & 31;
    float m = warpMax(v);
    if (lane == 0) red[wid] = m;
    __syncthreads();
    if (tid == 0) { float x = red[0]; for (int w = 1; w < 10; w++) x = fmaxf(x, red[w]); bmax = x; }
    __syncthreads();
    float mx = bmax;
    float q = (mx > 0.f) ? 384.f / mx : 1.f;
    g_S[(size_t)z * SPSP + (size_t)r * SP + tid] =
        (unsigned char)__nv_cvt_float_to_fp8(v * q, __NV_SATFINITE, __NV_E4M3);
    if (tid == 0) g_rs[z * SP + r] = 4096.f / q;
}

// ---------------- chain: persistent CTA per batch, pipelined fp8 matvec ----------------
__global__ void __launch_bounds__(640, 1) k_chain(float* __restrict__ out) {
    int b = blockIdx.x, tid = threadIdx.x;
    __shared__ uint32_t part[2][32][160];
    __shared__ __half2 ah2[SP];
    __shared__ float redp[20];
    __shared__ float s_sinv;
    __shared__ unsigned char sg[NTAU + 1];
    int lane = tid & 31, wid = tid >> 5;
    int iq = tid / 20;
    int cp = tid % 20;

    for (int i = tid; i < NTAU; i += 640) sg[i] = g_gram[b * NTAU + i];
    unsigned tg = g_tail[b];
    int o0 = g_o0[b];
    __syncthreads();
    int z0 = sg[0] >> 2;

    // ---- prologue: alpha0 = normalize(I * Bm[:,o0]) ----
    double ll = 0.0;
    float v0p = (tid < SP) ? g_I[tid] * g_BmT[o0][tid] : 0.f;
    float wsum = warpSum(v0p);
    if (lane == 0) redp[wid] = wsum;
    __syncthreads();
    if (tid == 0) {
        float x = 0.f;
        #pragma unroll
        for (int w = 0; w < 20; w++) x += redp[w];
        s_sinv = 1.f / x;
        ll = (double)logf(x);
    }
    __syncthreads();
    float* af = (float*)&part[0][0][0];
    if (tid < SP) af[tid] = v0p * s_sinv;
    __syncthreads();
    if (tid < 160) {
        float2 rsv = *(const float2*)&g_rs[z0 * SP + 2 * tid];
        float a0 = af[2 * tid] * rsv.x, a1 = af[2 * tid + 1] * rsv.y;
        ah2[2 * tid]     = __floats2half2_rn(a0, a0);
        ah2[2 * tid + 1] = __floats2half2_rn(a1, a1);
    }
    __syncthreads();

    // ---- preload matrix regs for step 0 ----
    uint4 mr[10];
    {
        const uint4* p = (const uint4*)(g_S + (size_t)z0 * SPSP) + tid;
        #pragma unroll
        for (int k = 0; k < 10; k++) mr[k] = __ldcg(p + k * 640);
    }

    for (int step = 0; step < NSTEP; ++step) {
        int pb = step & 1;
        int d, zn;
        if (step < NTAU) d = sg[step] & 3;
        else if (step == NTAU) d = (tg >> 2) & 3;
        else d = tg & 3;
        if (step + 1 < NTAU) zn = sg[step + 1] >> 2;
        else if (step + 1 == NTAU) zn = 64 + ((tg >> 4) & 3);
        else zn = 68;

        // ---- FMA phase (all threads) ----
        __half2 a0 = __floats2half2_rn(0.f, 0.f);
        __half2 a1 = a0, a2 = a0, a3 = a0, a4 = a0, a5 = a0, a6 = a0, a7 = a0;
        #pragma unroll
        for (int k = 0; k < 10; k++) {
            __half2 av = ah2[iq + 32 * k];
            uint32_t h0, h1;
            cvt2(mr[k].x, h0, h1);
            a0 = __hfma2(av, u2h(h0), a0);
            a1 = __hfma2(av, u2h(h1), a1);
            cvt2(mr[k].y, h0, h1);
            a2 = __hfma2(av, u2h(h0), a2);
            a3 = __hfma2(av, u2h(h1), a3);
            cvt2(mr[k].z, h0, h1);
            a4 = __hfma2(av, u2h(h0), a4);
            a5 = __hfma2(av, u2h(h1), a5);
            cvt2(mr[k].w, h0, h1);
            a6 = __hfma2(av, u2h(h0), a6);
            a7 = __hfma2(av, u2h(h1), a7);
        }
        uint32_t* dst = &part[pb][iq][cp * 8];
        *(uint4*)dst       = make_uint4(h2u(a0), h2u(a1), h2u(a2), h2u(a3));
        *(uint4*)(dst + 4) = make_uint4(h2u(a4), h2u(a5), h2u(a6), h2u(a7));

        if (tid < 160) {
            float2 rsv = *(const float2*)&g_rs[zn * SP + 2 * tid];  // prefetch
            BAR_SYNC(1, 640);                       // partials ready
            __half2 s2 = __floats2half2_rn(0.f, 0.f);
            #pragma unroll
            for (int k = 0; k < 32; k++)
                s2 = __hadd2(s2, *(const __half2*)&part[pb][k][tid]);
            float2 f2 = __half22float2(s2);
            float2 fo = *(const float2*)&g_BmT[d][2 * tid];
            float v0 = f2.x * fo.x, v1 = f2.y * fo.y;
            float t = warpSum(v0 + v1);
            if (lane == 0) redp[wid] = t;
            BAR_SYNC(3, 160);
            float stot = 0.f;
            if (wid == 0) {
                float x = (lane < 5) ? redp[lane] : 0.f;
                x = warpSum(x);
                if (lane == 0) { s_sinv = 1.f / x; stot = x; }
            }
            BAR_SYNC(3, 160);
            float si = s_sinv;
            float b0 = v0 * si * rsv.x, b1 = v1 * si * rsv.y;
            ah2[2 * tid]     = __floats2half2_rn(b0, b0);
            ah2[2 * tid + 1] = __floats2half2_rn(b1, b1);
            BAR_ARRIVE(2, 640);                     // alpha ready
            if (tid == 0) ll += (double)logf(stot);
        } else {
            BAR_ARRIVE(1, 640);
        }

        // ---- issue next step's loads ----
        {
            const uint4* p = (const uint4*)(g_S + (size_t)zn * SPSP) + tid;
            #pragma unroll
            for (int k = 0; k < 10; k++) mr[k] = __ldcg(p + k * 640);
        }
        if (tid >= 160) BAR_SYNC(2, 640);
    }
    if (tid == 0) out[b] = (float)(ll - (double)NSTEP * LOG_SCALE_D);
}

// ---------------- launch ----------------
extern "C" void kernel_launch(void* const* d_in, const int* in_sizes, int n_in,
                              void* d_out, int out_size) {
    const float* inputs = (const float*)d_in[0];
    const float* initk  = (const float*)d_in[1];
    const float* transk = (const float*)d_in[2];
    const float* emisk  = (const float*)d_in[3];
    float* out = (float*)d_out;

    k_setup<<<1, 512>>>(initk, emisk);
    k_softA<<<NS, 320>>>(transk);
    k_gram<<<NB, 256>>>(inputs);
    k_gemm<<<dim3(5, 5, 4), 256>>>(0);
    k_gemm<<<dim3(5, 5, 64), 256>>>(1);
    k_quant<<<dim3(320, 69), 320>>>();
    k_chain<<<NB, 640>>>(out);
}